// round 1
// baseline (speedup 1.0000x reference)
#include <cuda_runtime.h>
#include <cuda_bf16.h>

#define NN 100000
#define HH 4
#define CC 32
#define EE 1600000
#define IN_F 256
#define HC 128   // H*C
#define NEG_SLOPE 0.2f

// ---------------- device scratch (static, no allocation) ----------------
__device__ float g_feat[(size_t)NN * HC];   // 51.2 MB  [N,128]
__device__ float g_el[(size_t)NN * HH];     // [N,4]
__device__ float g_er[(size_t)NN * HH];     // [N,4]
__device__ float g_s[(size_t)NN * HH];      // [N,4] softmax denominators
__device__ float g_ex[(size_t)EE * HH];     // 25.6 MB [E,4] exp(e)
__device__ float g_acc[(size_t)NN * CC];    // 12.8 MB [N,32] head-summed aggregate

// ---------------- zero accumulators ----------------
__global__ void zero_kernel() {
    int i = blockIdx.x * blockDim.x + threadIdx.x;
    int total = NN * CC + NN * HH;
    if (i < NN * CC) g_acc[i] = 0.0f;
    else if (i < total) g_s[i - NN * CC] = 0.0f;
}

// ---------------- GEMM: feat = X @ W  (M=100000, N=128, K=256) ----------------
#define BM 128
#define BN 128
#define BK 16
__global__ __launch_bounds__(256) void gemm_kernel(const float* __restrict__ X,
                                                   const float* __restrict__ W) {
    __shared__ float As[BK][BM + 4];  // transposed A tile
    __shared__ float Bs[BK][BN];

    int tid = threadIdx.x;           // 256 threads
    int bm = blockIdx.x * BM;
    int tx = tid & 15;               // 16 thread cols
    int ty = tid >> 4;               // 16 thread rows

    float acc[8][8];
#pragma unroll
    for (int i = 0; i < 8; i++)
#pragma unroll
        for (int j = 0; j < 8; j++) acc[i][j] = 0.0f;

    for (int k0 = 0; k0 < IN_F; k0 += BK) {
        // load A tile: 128 rows x 16 cols = 512 float4, 2 per thread
#pragma unroll
        for (int i = 0; i < 2; i++) {
            int id = tid * 2 + i;
            int r = id >> 2;
            int c4 = (id & 3) * 4;
            int gr = bm + r;
            float4 v = make_float4(0.f, 0.f, 0.f, 0.f);
            if (gr < NN)
                v = *(const float4*)(X + (size_t)gr * IN_F + k0 + c4);
            As[c4 + 0][r] = v.x;
            As[c4 + 1][r] = v.y;
            As[c4 + 2][r] = v.z;
            As[c4 + 3][r] = v.w;
        }
        // load B tile: 16 rows x 128 cols = 512 float4, 2 per thread
#pragma unroll
        for (int i = 0; i < 2; i++) {
            int id = tid * 2 + i;
            int r = id >> 5;
            int c4 = (id & 31) * 4;
            float4 v = *(const float4*)(W + (size_t)(k0 + r) * HC + c4);
            *(float4*)&Bs[r][c4] = v;
        }
        __syncthreads();

#pragma unroll
        for (int k = 0; k < BK; k++) {
            float a[8], b[8];
            float4 a0 = *(const float4*)&As[k][ty * 8];
            float4 a1 = *(const float4*)&As[k][ty * 8 + 4];
            a[0]=a0.x; a[1]=a0.y; a[2]=a0.z; a[3]=a0.w;
            a[4]=a1.x; a[5]=a1.y; a[6]=a1.z; a[7]=a1.w;
            float4 b0 = *(const float4*)&Bs[k][tx * 8];
            float4 b1 = *(const float4*)&Bs[k][tx * 8 + 4];
            b[0]=b0.x; b[1]=b0.y; b[2]=b0.z; b[3]=b0.w;
            b[4]=b1.x; b[5]=b1.y; b[6]=b1.z; b[7]=b1.w;
#pragma unroll
            for (int i = 0; i < 8; i++)
#pragma unroll
                for (int j = 0; j < 8; j++) acc[i][j] += a[i] * b[j];
        }
        __syncthreads();
    }

    // write back
#pragma unroll
    for (int i = 0; i < 8; i++) {
        int gr = bm + ty * 8 + i;
        if (gr < NN) {
            float4 v0 = make_float4(acc[i][0], acc[i][1], acc[i][2], acc[i][3]);
            float4 v1 = make_float4(acc[i][4], acc[i][5], acc[i][6], acc[i][7]);
            *(float4*)(g_feat + (size_t)gr * HC + tx * 8) = v0;
            *(float4*)(g_feat + (size_t)gr * HC + tx * 8 + 4) = v1;
        }
    }
}

// ---------------- el/er: per-node, per-head dot products ----------------
__global__ void eler_kernel(const float* __restrict__ al, const float* __restrict__ ar) {
    int warp = (blockIdx.x * blockDim.x + threadIdx.x) >> 5;
    int lane = threadIdx.x & 31;
    if (warp >= NN) return;
    const float4* frow = (const float4*)(g_feat + (size_t)warp * HC);
    float4 f = frow[lane];                       // elements lane*4 .. lane*4+3 (one head per 8-lane group)
    float4 a_l = ((const float4*)al)[lane];
    float4 a_r = ((const float4*)ar)[lane];
    float pl = f.x * a_l.x + f.y * a_l.y + f.z * a_l.z + f.w * a_l.w;
    float pr = f.x * a_r.x + f.y * a_r.y + f.z * a_r.z + f.w * a_r.w;
    // reduce within each 8-lane group (one head each)
    pl += __shfl_xor_sync(0xFFFFFFFFu, pl, 4);
    pl += __shfl_xor_sync(0xFFFFFFFFu, pl, 2);
    pl += __shfl_xor_sync(0xFFFFFFFFu, pl, 1);
    pr += __shfl_xor_sync(0xFFFFFFFFu, pr, 4);
    pr += __shfl_xor_sync(0xFFFFFFFFu, pr, 2);
    pr += __shfl_xor_sync(0xFFFFFFFFu, pr, 1);
    if ((lane & 7) == 0) {
        int h = lane >> 3;
        g_el[warp * HH + h] = pl;
        g_er[warp * HH + h] = pr;
    }
}

// ---------------- edge pass 1: ex = exp(leaky(el[src]+er[dst])), s[dst] += ex ----------------
__device__ __forceinline__ float leaky_exp(float t) {
    float v = (t >= 0.f) ? t : NEG_SLOPE * t;
    return expf(v);
}

__global__ void edge1_kernel(const int* __restrict__ src, const int* __restrict__ dst) {
    int e = blockIdx.x * blockDim.x + threadIdx.x;
    if (e >= EE) return;
    int si = src[e];
    int di = dst[e];
    float4 l = *(const float4*)(g_el + (size_t)si * HH);
    float4 r = *(const float4*)(g_er + (size_t)di * HH);
    float4 ex;
    ex.x = leaky_exp(l.x + r.x);
    ex.y = leaky_exp(l.y + r.y);
    ex.z = leaky_exp(l.z + r.z);
    ex.w = leaky_exp(l.w + r.w);
    *(float4*)(g_ex + (size_t)e * HH) = ex;
    float* sp = g_s + (size_t)di * HH;
    asm volatile("red.global.add.v4.f32 [%0], {%1, %2, %3, %4};"
                 :: "l"(sp), "f"(ex.x), "f"(ex.y), "f"(ex.z), "f"(ex.w)
                 : "memory");
}

// ---------------- edge pass 2: acc[dst,c] += sum_h alpha[h] * feat[src,h,c] ----------------
// 8 lanes per edge, each lane handles 4 consecutive c via float4.
__global__ void edge2_kernel(const int* __restrict__ src, const int* __restrict__ dst) {
    int idx = blockIdx.x * blockDim.x + threadIdx.x;
    int e = idx >> 3;
    int l8 = idx & 7;
    if (e >= EE) return;
    int si = src[e];
    int di = dst[e];
    float4 exv = *(const float4*)(g_ex + (size_t)e * HH);
    float4 sv = *(const float4*)(g_s + (size_t)di * HH);
    float a0 = exv.x / sv.x;
    float a1 = exv.y / sv.y;
    float a2 = exv.z / sv.z;
    float a3 = exv.w / sv.w;
    const float4* f = (const float4*)(g_feat + (size_t)si * HC);
    float4 f0 = f[l8];          // head 0, c = l8*4..l8*4+3
    float4 f1 = f[8 + l8];      // head 1
    float4 f2 = f[16 + l8];     // head 2
    float4 f3 = f[24 + l8];     // head 3
    float4 r;
    r.x = a0 * f0.x + a1 * f1.x + a2 * f2.x + a3 * f3.x;
    r.y = a0 * f0.y + a1 * f1.y + a2 * f2.y + a3 * f3.y;
    r.z = a0 * f0.z + a1 * f1.z + a2 * f2.z + a3 * f3.z;
    r.w = a0 * f0.w + a1 * f1.w + a2 * f2.w + a3 * f3.w;
    float* ap = g_acc + (size_t)di * CC + l8 * 4;
    asm volatile("red.global.add.v4.f32 [%0], {%1, %2, %3, %4};"
                 :: "l"(ap), "f"(r.x), "f"(r.y), "f"(r.z), "f"(r.w)
                 : "memory");
}

// ---------------- final: out = relu(acc/H + mean_h bias) ----------------
__global__ void final_kernel(const float* __restrict__ bias, float* __restrict__ out) {
    int i = blockIdx.x * blockDim.x + threadIdx.x;
    if (i >= NN * CC) return;
    int c = i & (CC - 1);
    float b = 0.25f * (bias[c] + bias[CC + c] + bias[2 * CC + c] + bias[3 * CC + c]);
    float v = g_acc[i] * 0.25f + b;
    out[i] = fmaxf(v, 0.0f);
}

// ---------------- launch ----------------
extern "C" void kernel_launch(void* const* d_in, const int* in_sizes, int n_in,
                              void* d_out, int out_size) {
    const float* x      = (const float*)d_in[0];
    const int*   src    = (const int*)d_in[1];
    const int*   dst    = (const int*)d_in[2];
    const float* W      = (const float*)d_in[3];
    const float* attn_l = (const float*)d_in[4];
    const float* attn_r = (const float*)d_in[5];
    const float* bias   = (const float*)d_in[6];
    float* out = (float*)d_out;

    {   // zero accumulators
        int total = NN * CC + NN * HH;
        zero_kernel<<<(total + 255) / 256, 256>>>();
    }
    {   // GEMM
        int grid = (NN + BM - 1) / BM;
        gemm_kernel<<<grid, 256>>>(x, W);
    }
    {   // el/er
        int threads = NN * 32;
        eler_kernel<<<(threads + 255) / 256, 256>>>(attn_l, attn_r);
    }
    {   // edge pass 1
        edge1_kernel<<<(EE + 255) / 256, 256>>>(src, dst);
    }
    {   // edge pass 2
        int threads = EE * 8;
        edge2_kernel<<<(threads + 255) / 256, 256>>>(src, dst);
    }
    {   // final
        int threads = NN * CC;
        final_kernel<<<(threads + 255) / 256, 256>>>(bias, out);
    }
}

// round 2
// speedup vs baseline: 1.0808x; 1.0808x over previous
#include <cuda_runtime.h>
#include <cuda_fp16.h>
#include <cuda_bf16.h>

#define NN 100000
#define HH 4
#define CC 32
#define EE 1600000
#define IN_F 256
#define HC 128   // H*C
#define NEG_SLOPE 0.2f

// ---------------- device scratch (static, no allocation) ----------------
__device__ __half g_feat_h[(size_t)NN * HC];  // 25.6 MB [N,128] fp16 features
__device__ float g_el[(size_t)NN * HH];       // [N,4]
__device__ float g_er[(size_t)NN * HH];       // [N,4]
__device__ float g_s[(size_t)NN * HH];        // [N,4] softmax denominators
__device__ float g_ex[(size_t)EE * HH];       // 25.6 MB [E,4] exp(e)
__device__ float g_acc[(size_t)NN * CC];      // 12.8 MB [N,32] head-summed aggregate

// ---------------- zero accumulators ----------------
__global__ void zero_kernel() {
    int i = blockIdx.x * blockDim.x + threadIdx.x;
    int total = NN * CC + NN * HH;
    if (i < NN * CC) g_acc[i] = 0.0f;
    else if (i < total) g_s[i - NN * CC] = 0.0f;
}

// ---------------- GEMM: feat = X @ W  (M=100000, N=128, K=256) ----------------
// Packed f32x2 FMA (FFMA2) inner loop: 2x fp32 throughput vs FFMA-3reg.
// Epilogue: fp16 feat store + fused el/er per-head dot products.
#define BM 128
#define BN 128
#define BK 16

__device__ __forceinline__ unsigned long long pack_dup(float a) {
    unsigned long long r;
    asm("mov.b64 %0, {%1, %1};" : "=l"(r) : "f"(a));
    return r;
}
__device__ __forceinline__ void unpack2(unsigned long long v, float& lo, float& hi) {
    asm("mov.b64 {%0, %1}, %2;" : "=f"(lo), "=f"(hi) : "l"(v));
}
__device__ __forceinline__ void ffma2(unsigned long long& d, unsigned long long a,
                                      unsigned long long b) {
    asm("fma.rn.f32x2 %0, %1, %2, %0;" : "+l"(d) : "l"(a), "l"(b));
}

__global__ __launch_bounds__(256) void gemm_kernel(const float* __restrict__ X,
                                                   const float* __restrict__ W,
                                                   const float* __restrict__ al,
                                                   const float* __restrict__ ar) {
    __shared__ float As[BK][BM + 4];  // transposed A tile
    __shared__ float Bs[BK][BN];

    int tid = threadIdx.x;           // 256 threads
    int bm = blockIdx.x * BM;
    int tx = tid & 15;               // 16 thread cols (8 cols each)
    int ty = tid >> 4;               // 16 thread rows (8 rows each)

    // acc[i][j] holds fp32 pair (col 2j, 2j+1) for row i
    unsigned long long acc[8][4];
#pragma unroll
    for (int i = 0; i < 8; i++)
#pragma unroll
        for (int j = 0; j < 4; j++) acc[i][j] = 0ull;

    for (int k0 = 0; k0 < IN_F; k0 += BK) {
        // load A tile: 128 rows x 16 cols = 512 float4, 2 per thread
#pragma unroll
        for (int i = 0; i < 2; i++) {
            int id = tid * 2 + i;
            int r = id >> 2;
            int c4 = (id & 3) * 4;
            int gr = bm + r;
            float4 v = make_float4(0.f, 0.f, 0.f, 0.f);
            if (gr < NN)
                v = *(const float4*)(X + (size_t)gr * IN_F + k0 + c4);
            As[c4 + 0][r] = v.x;
            As[c4 + 1][r] = v.y;
            As[c4 + 2][r] = v.z;
            As[c4 + 3][r] = v.w;
        }
        // load B tile: 16 rows x 128 cols = 512 float4, 2 per thread
#pragma unroll
        for (int i = 0; i < 2; i++) {
            int id = tid * 2 + i;
            int r = id >> 5;
            int c4 = (id & 31) * 4;
            float4 v = *(const float4*)(W + (size_t)(k0 + r) * HC + c4);
            *(float4*)&Bs[r][c4] = v;
        }
        __syncthreads();

#pragma unroll
        for (int k = 0; k < BK; k++) {
            float4 a0 = *(const float4*)&As[k][ty * 8];
            float4 a1 = *(const float4*)&As[k][ty * 8 + 4];
            unsigned long long ad[8];
            ad[0] = pack_dup(a0.x); ad[1] = pack_dup(a0.y);
            ad[2] = pack_dup(a0.z); ad[3] = pack_dup(a0.w);
            ad[4] = pack_dup(a1.x); ad[5] = pack_dup(a1.y);
            ad[6] = pack_dup(a1.z); ad[7] = pack_dup(a1.w);
            const unsigned long long* bp =
                (const unsigned long long*)&Bs[k][tx * 8];
            unsigned long long b[4];
            b[0] = bp[0]; b[1] = bp[1]; b[2] = bp[2]; b[3] = bp[3];
#pragma unroll
            for (int i = 0; i < 8; i++)
#pragma unroll
                for (int j = 0; j < 4; j++) ffma2(acc[i][j], ad[i], b[j]);
        }
        __syncthreads();
    }

    // epilogue: unpack, store fp16 feat, fused el/er
    float4 alv0 = *(const float4*)(al + tx * 8);
    float4 alv1 = *(const float4*)(al + tx * 8 + 4);
    float4 arv0 = *(const float4*)(ar + tx * 8);
    float4 arv1 = *(const float4*)(ar + tx * 8 + 4);
    float alr[8] = {alv0.x, alv0.y, alv0.z, alv0.w, alv1.x, alv1.y, alv1.z, alv1.w};
    float arr[8] = {arv0.x, arv0.y, arv0.z, arv0.w, arv1.x, arv1.y, arv1.z, arv1.w};

    int lane = tid & 31;
    int head = tx >> 2;     // this thread's 8 cols all fall in one head

#pragma unroll
    for (int i = 0; i < 8; i++) {
        int gr = bm + ty * 8 + i;
        float f[8];
#pragma unroll
        for (int j = 0; j < 4; j++) unpack2(acc[i][j], f[2 * j], f[2 * j + 1]);

        if (gr < NN) {
            __half2 h0 = __floats2half2_rn(f[0], f[1]);
            __half2 h1 = __floats2half2_rn(f[2], f[3]);
            __half2 h2 = __floats2half2_rn(f[4], f[5]);
            __half2 h3 = __floats2half2_rn(f[6], f[7]);
            uint4 pk;
            pk.x = *(unsigned*)&h0; pk.y = *(unsigned*)&h1;
            pk.z = *(unsigned*)&h2; pk.w = *(unsigned*)&h3;
            *(uint4*)(g_feat_h + (size_t)gr * HC + tx * 8) = pk;
        }

        float pl = 0.f, pr = 0.f;
#pragma unroll
        for (int j = 0; j < 8; j++) {
            pl += f[j] * alr[j];
            pr += f[j] * arr[j];
        }
        // reduce across the 4 lanes (tx&3) sharing (row-group, head)
        pl += __shfl_xor_sync(0xFFFFFFFFu, pl, 1);
        pl += __shfl_xor_sync(0xFFFFFFFFu, pl, 2);
        pr += __shfl_xor_sync(0xFFFFFFFFu, pr, 1);
        pr += __shfl_xor_sync(0xFFFFFFFFu, pr, 2);
        if ((lane & 3) == 0 && gr < NN) {
            g_el[(size_t)gr * HH + head] = pl;
            g_er[(size_t)gr * HH + head] = pr;
        }
    }
}

// ---------------- edge pass 1: ex = exp(leaky(el[src]+er[dst])), s[dst] += ex ----------------
__device__ __forceinline__ float leaky_exp(float t) {
    float v = (t >= 0.f) ? t : NEG_SLOPE * t;
    return expf(v);
}

__global__ void edge1_kernel(const int* __restrict__ src, const int* __restrict__ dst) {
    int e = blockIdx.x * blockDim.x + threadIdx.x;
    if (e >= EE) return;
    int si = src[e];
    int di = dst[e];
    float4 l = *(const float4*)(g_el + (size_t)si * HH);
    float4 r = *(const float4*)(g_er + (size_t)di * HH);
    float4 ex;
    ex.x = leaky_exp(l.x + r.x);
    ex.y = leaky_exp(l.y + r.y);
    ex.z = leaky_exp(l.z + r.z);
    ex.w = leaky_exp(l.w + r.w);
    *(float4*)(g_ex + (size_t)e * HH) = ex;
    float* sp = g_s + (size_t)di * HH;
    asm volatile("red.global.add.v4.f32 [%0], {%1, %2, %3, %4};"
                 :: "l"(sp), "f"(ex.x), "f"(ex.y), "f"(ex.z), "f"(ex.w)
                 : "memory");
}

// ---------------- edge pass 2: acc[dst,c] += sum_h alpha[h] * feat_h[src,h,c] ----------------
// 8 lanes per edge, each lane handles 4 consecutive c (fp16 feat gather).
__global__ void edge2_kernel(const int* __restrict__ src, const int* __restrict__ dst) {
    int idx = blockIdx.x * blockDim.x + threadIdx.x;
    int e = idx >> 3;
    int l8 = idx & 7;
    if (e >= EE) return;
    int si = src[e];
    int di = dst[e];
    float4 exv = *(const float4*)(g_ex + (size_t)e * HH);
    float4 sv = *(const float4*)(g_s + (size_t)di * HH);
    float a0 = exv.x / sv.x;
    float a1 = exv.y / sv.y;
    float a2 = exv.z / sv.z;
    float a3 = exv.w / sv.w;
    const __half* fp = g_feat_h + (size_t)si * HC + l8 * 4;
    float rx = 0.f, ry = 0.f, rz = 0.f, rw = 0.f;
    float ah[4] = {a0, a1, a2, a3};
#pragma unroll
    for (int h = 0; h < 4; h++) {
        uint2 u = *(const uint2*)(fp + h * 32);
        __half2 p0 = *reinterpret_cast<__half2*>(&u.x);
        __half2 p1 = *reinterpret_cast<__half2*>(&u.y);
        float2 f0 = __half22float2(p0);
        float2 f1 = __half22float2(p1);
        rx += ah[h] * f0.x;
        ry += ah[h] * f0.y;
        rz += ah[h] * f1.x;
        rw += ah[h] * f1.y;
    }
    float* ap = g_acc + (size_t)di * CC + l8 * 4;
    asm volatile("red.global.add.v4.f32 [%0], {%1, %2, %3, %4};"
                 :: "l"(ap), "f"(rx), "f"(ry), "f"(rz), "f"(rw)
                 : "memory");
}

// ---------------- final: out = relu(acc/H + mean_h bias) ----------------
__global__ void final_kernel(const float* __restrict__ bias, float* __restrict__ out) {
    int i = blockIdx.x * blockDim.x + threadIdx.x;
    if (i >= NN * CC) return;
    int c = i & (CC - 1);
    float b = 0.25f * (bias[c] + bias[CC + c] + bias[2 * CC + c] + bias[3 * CC + c]);
    float v = g_acc[i] * 0.25f + b;
    out[i] = fmaxf(v, 0.0f);
}

// ---------------- launch ----------------
extern "C" void kernel_launch(void* const* d_in, const int* in_sizes, int n_in,
                              void* d_out, int out_size) {
    const float* x      = (const float*)d_in[0];
    const int*   src    = (const int*)d_in[1];
    const int*   dst    = (const int*)d_in[2];
    const float* W      = (const float*)d_in[3];
    const float* attn_l = (const float*)d_in[4];
    const float* attn_r = (const float*)d_in[5];
    const float* bias   = (const float*)d_in[6];
    float* out = (float*)d_out;

    {   // zero accumulators
        int total = NN * CC + NN * HH;
        zero_kernel<<<(total + 255) / 256, 256>>>();
    }
    {   // GEMM + fused el/er + fp16 feat store
        int grid = (NN + BM - 1) / BM;
        gemm_kernel<<<grid, 256>>>(x, W, attn_l, attn_r);
    }
    {   // edge pass 1
        edge1_kernel<<<(EE + 255) / 256, 256>>>(src, dst);
    }
    {   // edge pass 2
        long long threads = (long long)EE * 8;
        edge2_kernel<<<(int)((threads + 255) / 256), 256>>>(src, dst);
    }
    {   // final
        int threads = NN * CC;
        final_kernel<<<(threads + 255) / 256, 256>>>(bias, out);
    }
}

// round 3
// speedup vs baseline: 1.6774x; 1.5521x over previous
#include <cuda_runtime.h>
#include <cuda_fp16.h>
#include <cuda_bf16.h>

#define NN 100000
#define HH 4
#define CC 32
#define EE 1600000
#define IN_F 256
#define HC 128   // H*C
#define NEG_SLOPE 0.2f

// ---------------- device scratch (static, no allocation) ----------------
__device__ __half g_feat_h[(size_t)NN * HC];  // 25.6 MB [N,128] fp16 features
__device__ float g_el[(size_t)NN * HH];       // [N,4]
__device__ float g_er[(size_t)NN * HH];       // [N,4]
__device__ float g_s[(size_t)NN * HH];        // [N,4] softmax denominators
__device__ float g_ex[(size_t)EE * HH];       // 25.6 MB [E,4] exp(e)
__device__ float g_acc[(size_t)NN * CC];      // 12.8 MB [N,32] head-summed aggregate

// ---------------- zero accumulators ----------------
__global__ void zero_kernel() {
    int i = blockIdx.x * blockDim.x + threadIdx.x;
    int total = NN * CC + NN * HH;
    if (i < NN * CC) g_acc[i] = 0.0f;
    else if (i < total) g_s[i - NN * CC] = 0.0f;
}

// ---------------- GEMM: feat = X @ W via tf32 mma.sync ----------------
// M=100000 (BM=128/block), N=128 (full), K=256 (BK=32 stages).
// 256 threads = 8 warps in 4x2 grid; warp tile 32x64; m16n8k8 fragments.
#define BM 128
#define BK 32

__device__ __forceinline__ unsigned f2tf32(float f) {
    unsigned u;
    asm("cvt.rna.tf32.f32 %0, %1;" : "=r"(u) : "f"(f));
    return u;
}

__device__ __forceinline__ void mma_tf32(float* c, const unsigned* a, const unsigned* b) {
    asm volatile(
        "mma.sync.aligned.m16n8k8.row.col.f32.tf32.tf32.f32 "
        "{%0,%1,%2,%3}, {%4,%5,%6,%7}, {%8,%9}, {%0,%1,%2,%3};"
        : "+f"(c[0]), "+f"(c[1]), "+f"(c[2]), "+f"(c[3])
        : "r"(a[0]), "r"(a[1]), "r"(a[2]), "r"(a[3]), "r"(b[0]), "r"(b[1]));
}

__global__ __launch_bounds__(256) void gemm_kernel(const float* __restrict__ X,
                                                   const float* __restrict__ W,
                                                   const float* __restrict__ al,
                                                   const float* __restrict__ ar) {
    __shared__ unsigned As[BM][36];   // [128][32+4pad] tf32 bits, M-major
    __shared__ unsigned Bs[BK][136];  // [32][128+8pad] tf32 bits, K-major

    int tid = threadIdx.x;
    int warp = tid >> 5;
    int lane = tid & 31;
    int warpm = warp >> 1;   // 0..3 -> rows warpm*32
    int warpn = warp & 1;    // 0..1 -> cols warpn*64
    int g = lane >> 2;       // groupID 0..7
    int tig = lane & 3;      // thread-in-group 0..3
    int bm = blockIdx.x * BM;

    float c[2][8][4];
#pragma unroll
    for (int mt = 0; mt < 2; mt++)
#pragma unroll
        for (int nt = 0; nt < 8; nt++)
#pragma unroll
            for (int r = 0; r < 4; r++) c[mt][nt][r] = 0.0f;

    for (int k0 = 0; k0 < IN_F; k0 += BK) {
        // A tile: 128x32 floats = 1024 float4, 4 per thread
#pragma unroll
        for (int i = 0; i < 4; i++) {
            int f = i * 256 + tid;
            int r = f >> 3;
            int c4 = (f & 7) * 4;
            int gr = bm + r;
            float4 v = make_float4(0.f, 0.f, 0.f, 0.f);
            if (gr < NN) v = *(const float4*)(X + (size_t)gr * IN_F + k0 + c4);
            As[r][c4 + 0] = f2tf32(v.x);
            As[r][c4 + 1] = f2tf32(v.y);
            As[r][c4 + 2] = f2tf32(v.z);
            As[r][c4 + 3] = f2tf32(v.w);
        }
        // B tile: 32x128 floats = 1024 float4, 4 per thread
#pragma unroll
        for (int i = 0; i < 4; i++) {
            int f = i * 256 + tid;
            int r = f >> 5;
            int c4 = (f & 31) * 4;
            float4 v = *(const float4*)(W + (size_t)(k0 + r) * HC + c4);
            Bs[r][c4 + 0] = f2tf32(v.x);
            Bs[r][c4 + 1] = f2tf32(v.y);
            Bs[r][c4 + 2] = f2tf32(v.z);
            Bs[r][c4 + 3] = f2tf32(v.w);
        }
        __syncthreads();

#pragma unroll
        for (int ks = 0; ks < 4; ks++) {
            int kk = ks * 8;
            unsigned a[2][4], b[8][2];
#pragma unroll
            for (int mt = 0; mt < 2; mt++) {
                int row = warpm * 32 + mt * 16;
                a[mt][0] = As[row + g][kk + tig];
                a[mt][1] = As[row + g + 8][kk + tig];
                a[mt][2] = As[row + g][kk + tig + 4];
                a[mt][3] = As[row + g + 8][kk + tig + 4];
            }
#pragma unroll
            for (int nt = 0; nt < 8; nt++) {
                int col = warpn * 64 + nt * 8 + g;
                b[nt][0] = Bs[kk + tig][col];
                b[nt][1] = Bs[kk + tig + 4][col];
            }
#pragma unroll
            for (int mt = 0; mt < 2; mt++)
#pragma unroll
                for (int nt = 0; nt < 8; nt++) mma_tf32(c[mt][nt], a[mt], b[nt]);
        }
        __syncthreads();
    }

    // ---- epilogue: fp16 feat store + fused el/er ----
    // Thread owns cols col(nt) = warpn*64 + nt*8 + tig*2 (+1), rows mt*16 + rr*8 + g.
    // Preload attn weights for this thread's 16 cols.
    float alw[8][2], arw[8][2];
#pragma unroll
    for (int nt = 0; nt < 8; nt++) {
        int col = warpn * 64 + nt * 8 + tig * 2;
        alw[nt][0] = al[col];     alw[nt][1] = al[col + 1];
        arw[nt][0] = ar[col];     arw[nt][1] = ar[col + 1];
    }

#pragma unroll
    for (int mt = 0; mt < 2; mt++) {
#pragma unroll
        for (int rr = 0; rr < 2; rr++) {
            int row = bm + warpm * 32 + mt * 16 + rr * 8 + g;
            bool ok = (row < NN);
            float pl[2] = {0.f, 0.f}, pr[2] = {0.f, 0.f};
#pragma unroll
            for (int nt = 0; nt < 8; nt++) {
                float v0 = c[mt][nt][rr * 2];
                float v1 = c[mt][nt][rr * 2 + 1];
                int hh = nt >> 2;    // local head (0/1) within warpn half
                pl[hh] += v0 * alw[nt][0] + v1 * alw[nt][1];
                pr[hh] += v0 * arw[nt][0] + v1 * arw[nt][1];
                if (ok) {
                    __half2 hv = __floats2half2_rn(v0, v1);
                    int col = warpn * 64 + nt * 8 + tig * 2;
                    *(__half2*)(g_feat_h + (size_t)row * HC + col) = hv;
                }
            }
            // reduce across the 4 tig lanes sharing this (row, head-pair)
#pragma unroll
            for (int hh = 0; hh < 2; hh++) {
                pl[hh] += __shfl_xor_sync(0xFFFFFFFFu, pl[hh], 1);
                pl[hh] += __shfl_xor_sync(0xFFFFFFFFu, pl[hh], 2);
                pr[hh] += __shfl_xor_sync(0xFFFFFFFFu, pr[hh], 1);
                pr[hh] += __shfl_xor_sync(0xFFFFFFFFu, pr[hh], 2);
            }
            if (tig == 0 && ok) {
                int base = row * HH + warpn * 2;
                g_el[base + 0] = pl[0];
                g_el[base + 1] = pl[1];
                g_er[base + 0] = pr[0];
                g_er[base + 1] = pr[1];
            }
        }
    }
}

// ---------------- edge pass 1: ex = exp(leaky(el[src]+er[dst])), s[dst] += ex ----------------
__device__ __forceinline__ float leaky_exp(float t) {
    float v = (t >= 0.f) ? t : NEG_SLOPE * t;
    return expf(v);
}

__global__ void edge1_kernel(const int* __restrict__ src, const int* __restrict__ dst) {
    int e = blockIdx.x * blockDim.x + threadIdx.x;
    if (e >= EE) return;
    int si = src[e];
    int di = dst[e];
    float4 l = *(const float4*)(g_el + (size_t)si * HH);
    float4 r = *(const float4*)(g_er + (size_t)di * HH);
    float4 ex;
    ex.x = leaky_exp(l.x + r.x);
    ex.y = leaky_exp(l.y + r.y);
    ex.z = leaky_exp(l.z + r.z);
    ex.w = leaky_exp(l.w + r.w);
    *(float4*)(g_ex + (size_t)e * HH) = ex;
    float* sp = g_s + (size_t)di * HH;
    asm volatile("red.global.add.v4.f32 [%0], {%1, %2, %3, %4};"
                 :: "l"(sp), "f"(ex.x), "f"(ex.y), "f"(ex.z), "f"(ex.w)
                 : "memory");
}

// ---------------- edge pass 2: acc[dst,c] += sum_h alpha[h] * feat_h[src,h,c] ----------------
// 4 lanes per edge, each lane handles 8 consecutive c (16B fp16 gathers per head).
__global__ void edge2_kernel(const int* __restrict__ src, const int* __restrict__ dst) {
    int idx = blockIdx.x * blockDim.x + threadIdx.x;
    int e = idx >> 2;
    int l4 = idx & 3;
    if (e >= EE) return;
    int si = src[e];
    int di = dst[e];
    float4 exv = *(const float4*)(g_ex + (size_t)e * HH);
    float4 sv = *(const float4*)(g_s + (size_t)di * HH);
    float ah[4];
    ah[0] = __fdividef(exv.x, sv.x);
    ah[1] = __fdividef(exv.y, sv.y);
    ah[2] = __fdividef(exv.z, sv.z);
    ah[3] = __fdividef(exv.w, sv.w);
    const __half* fp = g_feat_h + (size_t)si * HC + l4 * 8;
    float r[8];
#pragma unroll
    for (int j = 0; j < 8; j++) r[j] = 0.f;
#pragma unroll
    for (int h = 0; h < 4; h++) {
        uint4 u = *(const uint4*)(fp + h * CC);
        float2 f0 = __half22float2(*reinterpret_cast<__half2*>(&u.x));
        float2 f1 = __half22float2(*reinterpret_cast<__half2*>(&u.y));
        float2 f2 = __half22float2(*reinterpret_cast<__half2*>(&u.z));
        float2 f3 = __half22float2(*reinterpret_cast<__half2*>(&u.w));
        r[0] += ah[h] * f0.x;  r[1] += ah[h] * f0.y;
        r[2] += ah[h] * f1.x;  r[3] += ah[h] * f1.y;
        r[4] += ah[h] * f2.x;  r[5] += ah[h] * f2.y;
        r[6] += ah[h] * f3.x;  r[7] += ah[h] * f3.y;
    }
    float* ap = g_acc + (size_t)di * CC + l4 * 8;
    asm volatile("red.global.add.v4.f32 [%0], {%1, %2, %3, %4};"
                 :: "l"(ap), "f"(r[0]), "f"(r[1]), "f"(r[2]), "f"(r[3])
                 : "memory");
    asm volatile("red.global.add.v4.f32 [%0], {%1, %2, %3, %4};"
                 :: "l"(ap + 4), "f"(r[4]), "f"(r[5]), "f"(r[6]), "f"(r[7])
                 : "memory");
}

// ---------------- final: out = relu(acc/H + mean_h bias) ----------------
__global__ void final_kernel(const float* __restrict__ bias, float* __restrict__ out) {
    int i = blockIdx.x * blockDim.x + threadIdx.x;
    if (i >= NN * CC) return;
    int c = i & (CC - 1);
    float b = 0.25f * (bias[c] + bias[CC + c] + bias[2 * CC + c] + bias[3 * CC + c]);
    float v = g_acc[i] * 0.25f + b;
    out[i] = fmaxf(v, 0.0f);
}

// ---------------- launch ----------------
extern "C" void kernel_launch(void* const* d_in, const int* in_sizes, int n_in,
                              void* d_out, int out_size) {
    const float* x      = (const float*)d_in[0];
    const int*   src    = (const int*)d_in[1];
    const int*   dst    = (const int*)d_in[2];
    const float* W      = (const float*)d_in[3];
    const float* attn_l = (const float*)d_in[4];
    const float* attn_r = (const float*)d_in[5];
    const float* bias   = (const float*)d_in[6];
    float* out = (float*)d_out;

    {   // zero accumulators
        int total = NN * CC + NN * HH;
        zero_kernel<<<(total + 255) / 256, 256>>>();
    }
    {   // tf32 MMA GEMM + fused el/er + fp16 feat store
        int grid = (NN + BM - 1) / BM;
        gemm_kernel<<<grid, 256>>>(x, W, attn_l, attn_r);
    }
    {   // edge pass 1
        edge1_kernel<<<(EE + 255) / 256, 256>>>(src, dst);
    }
    {   // edge pass 2
        long long threads = (long long)EE * 4;
        edge2_kernel<<<(int)((threads + 255) / 256), 256>>>(src, dst);
    }
    {   // final
        int threads = NN * CC;
        final_kernel<<<(threads + 255) / 256, 256>>>(bias, out);
    }
}